// round 1
// baseline (speedup 1.0000x reference)
#include <cuda_runtime.h>
#include <math.h>

// Problem constants
#define TOK   8192          // T = BS*SLEN
#define DIM   2048
#define HID   1792
#define NE    8
#define RROWS 16384         // T * TOPK
#define MAXROWS 17408       // RROWS + NE*128 padding headroom, multiple of 128
#define MAXTILES 136        // MAXROWS / 128

// ---------------- scratch (device globals; no allocation) ----------------
__device__ float g_routed_in[(size_t)MAXROWS * DIM];   // ~142.6 MB
__device__ float g_tmp1[(size_t)MAXROWS * HID];        // ~124.8 MB
__device__ float g_tmp2[(size_t)MAXROWS * HID];        // ~124.8 MB
__device__ float g_routed_out[(size_t)MAXROWS * DIM];  // ~142.6 MB
__device__ int   g_sel[RROWS];
__device__ int   g_pos[RROWS];
__device__ float g_tsc[RROWS];
__device__ int   g_counts[NE];
__device__ int   g_cursor[NE];
__device__ int   g_poff[NE + 1];
__device__ int   g_tile2e[MAXTILES];
__device__ int   g_nrowtiles;

// ---------------- tiny kernels ----------------
__global__ void zero_counts_kernel() {
    int i = threadIdx.x;
    if (i < NE) g_counts[i] = 0;
}

// One warp per token: logits = x_t . gate_w[:, e] for e=0..7, softmax, top-2.
__global__ void router_kernel(const float* __restrict__ x,
                              const float* __restrict__ gw,
                              const float* __restrict__ eb) {
    int gid  = blockIdx.x * blockDim.x + threadIdx.x;
    int t    = gid >> 5;
    int lane = gid & 31;
    const float* xr = x + (size_t)t * DIM;

    float a0=0.f,a1=0.f,a2=0.f,a3=0.f,a4=0.f,a5=0.f,a6=0.f,a7=0.f;
    for (int d = lane; d < DIM; d += 32) {
        float xv = xr[d];
        float4 g0 = *(const float4*)(gw + (size_t)d * NE);
        float4 g1 = *(const float4*)(gw + (size_t)d * NE + 4);
        a0 += xv * g0.x; a1 += xv * g0.y; a2 += xv * g0.z; a3 += xv * g0.w;
        a4 += xv * g1.x; a5 += xv * g1.y; a6 += xv * g1.z; a7 += xv * g1.w;
    }
    #pragma unroll
    for (int off = 16; off > 0; off >>= 1) {
        a0 += __shfl_xor_sync(0xFFFFFFFFu, a0, off);
        a1 += __shfl_xor_sync(0xFFFFFFFFu, a1, off);
        a2 += __shfl_xor_sync(0xFFFFFFFFu, a2, off);
        a3 += __shfl_xor_sync(0xFFFFFFFFu, a3, off);
        a4 += __shfl_xor_sync(0xFFFFFFFFu, a4, off);
        a5 += __shfl_xor_sync(0xFFFFFFFFu, a5, off);
        a6 += __shfl_xor_sync(0xFFFFFFFFu, a6, off);
        a7 += __shfl_xor_sync(0xFFFFFFFFu, a7, off);
    }
    if (lane == 0) {
        float lg[NE] = {a0,a1,a2,a3,a4,a5,a6,a7};
        float m = lg[0];
        #pragma unroll
        for (int e = 1; e < NE; e++) m = fmaxf(m, lg[e]);
        float se = 0.f, sc[NE];
        #pragma unroll
        for (int e = 0; e < NE; e++) { sc[e] = expf(lg[e] - m); se += sc[e]; }
        float inv = 1.f / se;
        #pragma unroll
        for (int e = 0; e < NE; e++) sc[e] *= inv;

        // top-2 on (score + bias), lowest index wins ties
        float best = -1e30f, second = -1e30f;
        int bi = 0, si = 0;
        #pragma unroll
        for (int e = 0; e < NE; e++) {
            float v = sc[e] + eb[e];
            if (v > best) { second = best; si = bi; best = v; bi = e; }
            else if (v > second) { second = v; si = e; }
        }
        g_sel[2 * t]     = bi;
        g_sel[2 * t + 1] = si;
        g_tsc[2 * t]     = sc[bi];   // bias-free scores
        g_tsc[2 * t + 1] = sc[si];
        atomicAdd(&g_counts[bi], 1);
        atomicAdd(&g_counts[si], 1);
    }
}

// Single-thread: padded segment offsets, tile->expert map, cursors.
__global__ void offsets_kernel() {
    if (threadIdx.x == 0 && blockIdx.x == 0) {
        int po = 0;
        for (int e = 0; e < NE; e++) {
            g_poff[e]   = po;
            g_cursor[e] = po;
            int tl = (g_counts[e] + 127) >> 7;
            for (int tt = 0; tt < tl; tt++) g_tile2e[(po >> 7) + tt] = e;
            po += tl << 7;
        }
        g_poff[NE] = po;
        g_nrowtiles = po >> 7;
    }
}

// Zero padding rows of routed_in (rows inside a segment but beyond its count).
__global__ void zeropad_kernel() {
    int r = blockIdx.x;
    if (r >= g_poff[NE]) return;
    int e = g_tile2e[r >> 7];
    if (r < g_poff[e] + g_counts[e]) return;
    float4 z = make_float4(0.f, 0.f, 0.f, 0.f);
    float4* dst = (float4*)(g_routed_in + (size_t)r * DIM);
    for (int i = threadIdx.x; i < DIM / 4; i += blockDim.x) dst[i] = z;
}

// One block per routed row: claim a slot in the expert segment, gather+scale.
__global__ void dispatch_kernel(const float* __restrict__ x) {
    __shared__ int sp;
    __shared__ float ss;
    int f = blockIdx.x;
    int t = f >> 1;
    if (threadIdx.x == 0) {
        int e = g_sel[f];
        int p = atomicAdd(&g_cursor[e], 1);
        g_pos[f] = p;
        sp = p; ss = g_tsc[f];
    }
    __syncthreads();
    int p = sp; float s = ss;
    const float4* src = (const float4*)(x + (size_t)t * DIM);
    float4* dst = (float4*)(g_routed_in + (size_t)p * DIM);
    for (int i = threadIdx.x; i < DIM / 4; i += blockDim.x) {
        float4 v = src[i];
        v.x *= s; v.y *= s; v.z *= s; v.w *= s;
        dst[i] = v;
    }
}

// o = silu(a) * b, elementwise, float4
__global__ void silu_mul_kernel(const float* __restrict__ a,
                                const float* __restrict__ b,
                                float* __restrict__ o, long n4) {
    long i = (long)blockIdx.x * blockDim.x + threadIdx.x;
    long stride = (long)gridDim.x * blockDim.x;
    for (; i < n4; i += stride) {
        float4 va = ((const float4*)a)[i];
        float4 vb = ((const float4*)b)[i];
        float4 vo;
        vo.x = va.x / (1.f + expf(-va.x)) * vb.x;
        vo.y = va.y / (1.f + expf(-va.y)) * vb.y;
        vo.z = va.z / (1.f + expf(-va.z)) * vb.z;
        vo.w = va.w / (1.f + expf(-va.w)) * vb.w;
        ((float4*)o)[i] = vo;
    }
}

// out[t] += routed_out[posA] + routed_out[posB]  (no atomics, deterministic)
__global__ void combine_kernel(float* __restrict__ out) {
    int t = blockIdx.x;
    int pa = g_pos[2 * t];
    int pb = g_pos[2 * t + 1];
    float4* o = (float4*)(out + (size_t)t * DIM);
    const float4* ra = (const float4*)(g_routed_out + (size_t)pa * DIM);
    const float4* rb = (const float4*)(g_routed_out + (size_t)pb * DIM);
    for (int i = threadIdx.x; i < DIM / 4; i += blockDim.x) {
        float4 v = o[i], va = ra[i], vb = rb[i];
        v.x += va.x + vb.x;
        v.y += va.y + vb.y;
        v.z += va.z + vb.z;
        v.w += va.w + vb.w;
        o[i] = v;
    }
}

// ---------------- SGEMM: C[M,N] = A[M,K] @ B[K,N] (all row-major, fp32) ----
// 128x128 tile, BK=16, 256 threads, 8x8 per-thread, double-buffered smem.
// GROUPED: row-tile mt uses B + tile2e[mt]*estride, skips tiles >= g_nrowtiles.
template <bool GROUPED>
__global__ void __launch_bounds__(256, 2)
sgemm128_kernel(const float* __restrict__ A, const float* __restrict__ B,
                float* __restrict__ C, int N, int K, size_t estride) {
    const int BM = 128, BN = 128, BK = 16;
    int mt = blockIdx.y, nt = blockIdx.x;
    if (GROUPED) {
        if (mt >= g_nrowtiles) return;
        B += (size_t)g_tile2e[mt] * estride;
    }

    __shared__ float As[2][BK][BM];
    __shared__ float Bs[2][BK][BN];

    int tid  = threadIdx.x;
    int arow = tid >> 2;              // 0..63 (rows arow, arow+64)
    int acol = (tid & 3) << 2;        // 0,4,8,12
    int brow = tid >> 5;              // 0..7 (rows brow, brow+8)
    int bcol = (tid & 31) << 2;       // 0..124

    const float* Ag = A + (size_t)mt * BM * K;
    const float* Bg = B + (size_t)nt * BN;

    float acc[8][8];
    #pragma unroll
    for (int i = 0; i < 8; i++)
        #pragma unroll
        for (int j = 0; j < 8; j++) acc[i][j] = 0.f;

    int nk = K >> 4;
    float4 a0, a1, b0, b1;

    // prologue: tile 0
    a0 = *(const float4*)(Ag + (size_t)arow * K + acol);
    a1 = *(const float4*)(Ag + (size_t)(arow + 64) * K + acol);
    b0 = *(const float4*)(Bg + (size_t)brow * N + bcol);
    b1 = *(const float4*)(Bg + (size_t)(brow + 8) * N + bcol);
    As[0][acol + 0][arow] = a0.x; As[0][acol + 1][arow] = a0.y;
    As[0][acol + 2][arow] = a0.z; As[0][acol + 3][arow] = a0.w;
    As[0][acol + 0][arow + 64] = a1.x; As[0][acol + 1][arow + 64] = a1.y;
    As[0][acol + 2][arow + 64] = a1.z; As[0][acol + 3][arow + 64] = a1.w;
    *(float4*)&Bs[0][brow][bcol]     = b0;
    *(float4*)&Bs[0][brow + 8][bcol] = b1;
    __syncthreads();

    int ty = tid >> 4, tx = tid & 15;

    for (int kt = 0; kt < nk; kt++) {
        int buf = kt & 1;
        if (kt + 1 < nk) {
            const float* pa = Ag + (size_t)(kt + 1) * BK;
            a0 = *(const float4*)(pa + (size_t)arow * K + acol);
            a1 = *(const float4*)(pa + (size_t)(arow + 64) * K + acol);
            const float* pb = Bg + (size_t)(kt + 1) * BK * N;
            b0 = *(const float4*)(pb + (size_t)brow * N + bcol);
            b1 = *(const float4*)(pb + (size_t)(brow + 8) * N + bcol);
        }
        #pragma unroll
        for (int k = 0; k < BK; k++) {
            float ra[8], rb[8];
            *(float4*)&ra[0] = *(const float4*)&As[buf][k][ty * 8];
            *(float4*)&ra[4] = *(const float4*)&As[buf][k][ty * 8 + 4];
            *(float4*)&rb[0] = *(const float4*)&Bs[buf][k][tx * 8];
            *(float4*)&rb[4] = *(const float4*)&Bs[buf][k][tx * 8 + 4];
            #pragma unroll
            for (int i = 0; i < 8; i++)
                #pragma unroll
                for (int j = 0; j < 8; j++) acc[i][j] += ra[i] * rb[j];
        }
        if (kt + 1 < nk) {
            int nb = buf ^ 1;
            As[nb][acol + 0][arow] = a0.x; As[nb][acol + 1][arow] = a0.y;
            As[nb][acol + 2][arow] = a0.z; As[nb][acol + 3][arow] = a0.w;
            As[nb][acol + 0][arow + 64] = a1.x; As[nb][acol + 1][arow + 64] = a1.y;
            As[nb][acol + 2][arow + 64] = a1.z; As[nb][acol + 3][arow + 64] = a1.w;
            *(float4*)&Bs[nb][brow][bcol]     = b0;
            *(float4*)&Bs[nb][brow + 8][bcol] = b1;
            __syncthreads();
        }
    }

    float* Cp = C + (size_t)(mt * BM + ty * 8) * N + (size_t)nt * BN + tx * 8;
    #pragma unroll
    for (int i = 0; i < 8; i++) {
        *(float4*)(Cp + (size_t)i * N)     = make_float4(acc[i][0], acc[i][1], acc[i][2], acc[i][3]);
        *(float4*)(Cp + (size_t)i * N + 4) = make_float4(acc[i][4], acc[i][5], acc[i][6], acc[i][7]);
    }
}

// ---------------- launch ----------------
extern "C" void kernel_launch(void* const* d_in, const int* in_sizes, int n_in,
                              void* d_out, int out_size) {
    const float* x      = (const float*)d_in[0];
    const float* gate_w = (const float*)d_in[1];
    const float* w1     = (const float*)d_in[2];
    const float* w2     = (const float*)d_in[3];
    const float* w3     = (const float*)d_in[4];
    const float* sw1    = (const float*)d_in[5];
    const float* sw2    = (const float*)d_in[6];
    const float* sw3    = (const float*)d_in[7];
    const float* eb     = (const float*)d_in[8];
    float* out = (float*)d_out;

    void *pri, *pt1, *pt2, *pro;
    cudaGetSymbolAddress(&pri, g_routed_in);
    cudaGetSymbolAddress(&pt1, g_tmp1);
    cudaGetSymbolAddress(&pt2, g_tmp2);
    cudaGetSymbolAddress(&pro, g_routed_out);
    float* RI = (float*)pri;
    float* T1 = (float*)pt1;
    float* T2 = (float*)pt2;
    float* RO = (float*)pro;

    // routing
    zero_counts_kernel<<<1, 32>>>();
    router_kernel<<<TOK / 8, 256>>>(x, gate_w, eb);
    offsets_kernel<<<1, 1>>>();
    zeropad_kernel<<<MAXROWS, 256>>>();
    dispatch_kernel<<<RROWS, 256>>>(x);

    // routed experts: h = silu(RI@w1) * (RI@w3); RO = h @ w2
    dim3 gRH(HID / 128, MAXTILES);   // N=HID tiles x row tiles
    dim3 gRD(DIM / 128, MAXTILES);
    sgemm128_kernel<true><<<gRH, 256>>>(RI, w1, T1, HID, DIM, (size_t)DIM * HID);
    sgemm128_kernel<true><<<gRH, 256>>>(RI, w3, T2, HID, DIM, (size_t)DIM * HID);
    silu_mul_kernel<<<(int)(((size_t)MAXROWS * HID / 4) / 256), 256>>>(
        T1, T2, T1, (long)MAXROWS * HID / 4);
    sgemm128_kernel<true><<<gRD, 256>>>(T1, w2, RO, DIM, HID, (size_t)HID * DIM);

    // shared expert: out = (silu(x@sw1) * (x@sw3)) @ sw2
    dim3 gSH(HID / 128, TOK / 128);
    dim3 gSD(DIM / 128, TOK / 128);
    sgemm128_kernel<false><<<gSH, 256>>>(x, sw1, T2, HID, DIM, 0);
    sgemm128_kernel<false><<<gSH, 256>>>(x, sw3, T1, HID, DIM, 0);
    silu_mul_kernel<<<(int)(((size_t)TOK * HID / 4) / 256), 256>>>(
        T2, T1, T2, (long)TOK * HID / 4);
    sgemm128_kernel<false><<<gSD, 256>>>(T2, sw2, out, DIM, HID, 0);

    // combine routed contributions into out (deterministic, no atomics)
    combine_kernel<<<TOK, 256>>>(out);
}

// round 2
// speedup vs baseline: 1.0014x; 1.0014x over previous
#include <cuda_runtime.h>
#include <math.h>

// Problem constants
#define TOK   8192          // T = BS*SLEN
#define DIM   2048
#define HID   1792
#define NE    8
#define RROWS 16384         // T * TOPK
#define MAXROWS 17408       // RROWS + NE*128 padding headroom, multiple of 128
#define MAXTILES 136        // MAXROWS / 128

// ---------------- scratch (device globals; no allocation) ----------------
__device__ float g_routed_in[(size_t)MAXROWS * DIM];   // ~142.6 MB
__device__ float g_tmp1[(size_t)MAXROWS * HID];        // ~124.8 MB
__device__ float g_tmp2[(size_t)MAXROWS * HID];        // ~124.8 MB
__device__ float g_routed_out[(size_t)MAXROWS * DIM];  // ~142.6 MB
__device__ int   g_sel[RROWS];
__device__ int   g_pos[RROWS];
__device__ float g_tsc[RROWS];
__device__ int   g_counts[NE];
__device__ int   g_cursor[NE];
__device__ int   g_poff[NE + 1];
__device__ int   g_tile2e[MAXTILES];
__device__ int   g_nrowtiles;

// ---------------- tiny kernels ----------------
__global__ void zero_counts_kernel() {
    int i = threadIdx.x;
    if (i < NE) g_counts[i] = 0;
}

// One warp per token: logits = x_t . gate_w[:, e] for e=0..7, softmax, top-2.
__global__ void router_kernel(const float* __restrict__ x,
                              const float* __restrict__ gw,
                              const float* __restrict__ eb) {
    int gid  = blockIdx.x * blockDim.x + threadIdx.x;
    int t    = gid >> 5;
    int lane = gid & 31;
    const float* xr = x + (size_t)t * DIM;

    float a0=0.f,a1=0.f,a2=0.f,a3=0.f,a4=0.f,a5=0.f,a6=0.f,a7=0.f;
    for (int d = lane; d < DIM; d += 32) {
        float xv = xr[d];
        float4 g0 = *(const float4*)(gw + (size_t)d * NE);
        float4 g1 = *(const float4*)(gw + (size_t)d * NE + 4);
        a0 += xv * g0.x; a1 += xv * g0.y; a2 += xv * g0.z; a3 += xv * g0.w;
        a4 += xv * g1.x; a5 += xv * g1.y; a6 += xv * g1.z; a7 += xv * g1.w;
    }
    #pragma unroll
    for (int off = 16; off > 0; off >>= 1) {
        a0 += __shfl_xor_sync(0xFFFFFFFFu, a0, off);
        a1 += __shfl_xor_sync(0xFFFFFFFFu, a1, off);
        a2 += __shfl_xor_sync(0xFFFFFFFFu, a2, off);
        a3 += __shfl_xor_sync(0xFFFFFFFFu, a3, off);
        a4 += __shfl_xor_sync(0xFFFFFFFFu, a4, off);
        a5 += __shfl_xor_sync(0xFFFFFFFFu, a5, off);
        a6 += __shfl_xor_sync(0xFFFFFFFFu, a6, off);
        a7 += __shfl_xor_sync(0xFFFFFFFFu, a7, off);
    }
    if (lane == 0) {
        float lg[NE] = {a0,a1,a2,a3,a4,a5,a6,a7};
        float m = lg[0];
        #pragma unroll
        for (int e = 1; e < NE; e++) m = fmaxf(m, lg[e]);
        float se = 0.f, sc[NE];
        #pragma unroll
        for (int e = 0; e < NE; e++) { sc[e] = expf(lg[e] - m); se += sc[e]; }
        float inv = 1.f / se;
        #pragma unroll
        for (int e = 0; e < NE; e++) sc[e] *= inv;

        // top-2 on (score + bias), lowest index wins ties
        float best = -1e30f, second = -1e30f;
        int bi = 0, si = 0;
        #pragma unroll
        for (int e = 0; e < NE; e++) {
            float v = sc[e] + eb[e];
            if (v > best) { second = best; si = bi; best = v; bi = e; }
            else if (v > second) { second = v; si = e; }
        }
        g_sel[2 * t]     = bi;
        g_sel[2 * t + 1] = si;
        g_tsc[2 * t]     = sc[bi];   // bias-free scores
        g_tsc[2 * t + 1] = sc[si];
        atomicAdd(&g_counts[bi], 1);
        atomicAdd(&g_counts[si], 1);
    }
}

// Single-thread: padded segment offsets, tile->expert map, cursors.
__global__ void offsets_kernel() {
    if (threadIdx.x == 0 && blockIdx.x == 0) {
        int po = 0;
        for (int e = 0; e < NE; e++) {
            g_poff[e]   = po;
            g_cursor[e] = po;
            int tl = (g_counts[e] + 127) >> 7;
            for (int tt = 0; tt < tl; tt++) g_tile2e[(po >> 7) + tt] = e;
            po += tl << 7;
        }
        g_poff[NE] = po;
        g_nrowtiles = po >> 7;
    }
}

// Zero padding rows of routed_in (rows inside a segment but beyond its count).
__global__ void zeropad_kernel() {
    int r = blockIdx.x;
    if (r >= g_poff[NE]) return;
    int e = g_tile2e[r >> 7];
    if (r < g_poff[e] + g_counts[e]) return;
    float4 z = make_float4(0.f, 0.f, 0.f, 0.f);
    float4* dst = (float4*)(g_routed_in + (size_t)r * DIM);
    for (int i = threadIdx.x; i < DIM / 4; i += blockDim.x) dst[i] = z;
}

// One block per routed row: claim a slot in the expert segment, gather+scale.
__global__ void dispatch_kernel(const float* __restrict__ x) {
    __shared__ int sp;
    __shared__ float ss;
    int f = blockIdx.x;
    int t = f >> 1;
    if (threadIdx.x == 0) {
        int e = g_sel[f];
        int p = atomicAdd(&g_cursor[e], 1);
        g_pos[f] = p;
        sp = p; ss = g_tsc[f];
    }
    __syncthreads();
    int p = sp; float s = ss;
    const float4* src = (const float4*)(x + (size_t)t * DIM);
    float4* dst = (float4*)(g_routed_in + (size_t)p * DIM);
    for (int i = threadIdx.x; i < DIM / 4; i += blockDim.x) {
        float4 v = src[i];
        v.x *= s; v.y *= s; v.z *= s; v.w *= s;
        dst[i] = v;
    }
}

// o = silu(a) * b, elementwise, float4
__global__ void silu_mul_kernel(const float* __restrict__ a,
                                const float* __restrict__ b,
                                float* __restrict__ o, long n4) {
    long i = (long)blockIdx.x * blockDim.x + threadIdx.x;
    long stride = (long)gridDim.x * blockDim.x;
    for (; i < n4; i += stride) {
        float4 va = ((const float4*)a)[i];
        float4 vb = ((const float4*)b)[i];
        float4 vo;
        vo.x = va.x / (1.f + expf(-va.x)) * vb.x;
        vo.y = va.y / (1.f + expf(-va.y)) * vb.y;
        vo.z = va.z / (1.f + expf(-va.z)) * vb.z;
        vo.w = va.w / (1.f + expf(-va.w)) * vb.w;
        ((float4*)o)[i] = vo;
    }
}

// out[t] += routed_out[posA] + routed_out[posB]  (no atomics, deterministic)
__global__ void combine_kernel(float* __restrict__ out) {
    int t = blockIdx.x;
    int pa = g_pos[2 * t];
    int pb = g_pos[2 * t + 1];
    float4* o = (float4*)(out + (size_t)t * DIM);
    const float4* ra = (const float4*)(g_routed_out + (size_t)pa * DIM);
    const float4* rb = (const float4*)(g_routed_out + (size_t)pb * DIM);
    for (int i = threadIdx.x; i < DIM / 4; i += blockDim.x) {
        float4 v = o[i], va = ra[i], vb = rb[i];
        v.x += va.x + vb.x;
        v.y += va.y + vb.y;
        v.z += va.z + vb.z;
        v.w += va.w + vb.w;
        o[i] = v;
    }
}

// ---------------- SGEMM: C[M,N] = A[M,K] @ B[K,N] (all row-major, fp32) ----
// 128x128 tile, BK=16, 256 threads, 8x8 per-thread, double-buffered smem.
// GROUPED: row-tile mt uses B + tile2e[mt]*estride, skips tiles >= g_nrowtiles.
template <bool GROUPED>
__global__ void __launch_bounds__(256, 2)
sgemm128_kernel(const float* __restrict__ A, const float* __restrict__ B,
                float* __restrict__ C, int N, int K, size_t estride) {
    const int BM = 128, BN = 128, BK = 16;
    int mt = blockIdx.y, nt = blockIdx.x;
    if (GROUPED) {
        if (mt >= g_nrowtiles) return;
        B += (size_t)g_tile2e[mt] * estride;
    }

    __shared__ float As[2][BK][BM];
    __shared__ float Bs[2][BK][BN];

    int tid  = threadIdx.x;
    int arow = tid >> 2;              // 0..63 (rows arow, arow+64)
    int acol = (tid & 3) << 2;        // 0,4,8,12
    int brow = tid >> 5;              // 0..7 (rows brow, brow+8)
    int bcol = (tid & 31) << 2;       // 0..124

    const float* Ag = A + (size_t)mt * BM * K;
    const float* Bg = B + (size_t)nt * BN;

    float acc[8][8];
    #pragma unroll
    for (int i = 0; i < 8; i++)
        #pragma unroll
        for (int j = 0; j < 8; j++) acc[i][j] = 0.f;

    int nk = K >> 4;
    float4 a0, a1, b0, b1;

    // prologue: tile 0
    a0 = *(const float4*)(Ag + (size_t)arow * K + acol);
    a1 = *(const float4*)(Ag + (size_t)(arow + 64) * K + acol);
    b0 = *(const float4*)(Bg + (size_t)brow * N + bcol);
    b1 = *(const float4*)(Bg + (size_t)(brow + 8) * N + bcol);
    As[0][acol + 0][arow] = a0.x; As[0][acol + 1][arow] = a0.y;
    As[0][acol + 2][arow] = a0.z; As[0][acol + 3][arow] = a0.w;
    As[0][acol + 0][arow + 64] = a1.x; As[0][acol + 1][arow + 64] = a1.y;
    As[0][acol + 2][arow + 64] = a1.z; As[0][acol + 3][arow + 64] = a1.w;
    *(float4*)&Bs[0][brow][bcol]     = b0;
    *(float4*)&Bs[0][brow + 8][bcol] = b1;
    __syncthreads();

    int ty = tid >> 4, tx = tid & 15;

    for (int kt = 0; kt < nk; kt++) {
        int buf = kt & 1;
        if (kt + 1 < nk) {
            const float* pa = Ag + (size_t)(kt + 1) * BK;
            a0 = *(const float4*)(pa + (size_t)arow * K + acol);
            a1 = *(const float4*)(pa + (size_t)(arow + 64) * K + acol);
            const float* pb = Bg + (size_t)(kt + 1) * BK * N;
            b0 = *(const float4*)(pb + (size_t)brow * N + bcol);
            b1 = *(const float4*)(pb + (size_t)(brow + 8) * N + bcol);
        }
        #pragma unroll
        for (int k = 0; k < BK; k++) {
            float ra[8], rb[8];
            *(float4*)&ra[0] = *(const float4*)&As[buf][k][ty * 8];
            *(float4*)&ra[4] = *(const float4*)&As[buf][k][ty * 8 + 4];
            *(float4*)&rb[0] = *(const float4*)&Bs[buf][k][tx * 8];
            *(float4*)&rb[4] = *(const float4*)&Bs[buf][k][tx * 8 + 4];
            #pragma unroll
            for (int i = 0; i < 8; i++)
                #pragma unroll
                for (int j = 0; j < 8; j++) acc[i][j] += ra[i] * rb[j];
        }
        if (kt + 1 < nk) {
            int nb = buf ^ 1;
            As[nb][acol + 0][arow] = a0.x; As[nb][acol + 1][arow] = a0.y;
            As[nb][acol + 2][arow] = a0.z; As[nb][acol + 3][arow] = a0.w;
            As[nb][acol + 0][arow + 64] = a1.x; As[nb][acol + 1][arow + 64] = a1.y;
            As[nb][acol + 2][arow + 64] = a1.z; As[nb][acol + 3][arow + 64] = a1.w;
            *(float4*)&Bs[nb][brow][bcol]     = b0;
            *(float4*)&Bs[nb][brow + 8][bcol] = b1;
            __syncthreads();
        }
    }

    float* Cp = C + (size_t)(mt * BM + ty * 8) * N + (size_t)nt * BN + tx * 8;
    #pragma unroll
    for (int i = 0; i < 8; i++) {
        *(float4*)(Cp + (size_t)i * N)     = make_float4(acc[i][0], acc[i][1], acc[i][2], acc[i][3]);
        *(float4*)(Cp + (size_t)i * N + 4) = make_float4(acc[i][4], acc[i][5], acc[i][6], acc[i][7]);
    }
}

// ---------------- launch ----------------
extern "C" void kernel_launch(void* const* d_in, const int* in_sizes, int n_in,
                              void* d_out, int out_size) {
    const float* x      = (const float*)d_in[0];
    const float* gate_w = (const float*)d_in[1];
    const float* w1     = (const float*)d_in[2];
    const float* w2     = (const float*)d_in[3];
    const float* w3     = (const float*)d_in[4];
    const float* sw1    = (const float*)d_in[5];
    const float* sw2    = (const float*)d_in[6];
    const float* sw3    = (const float*)d_in[7];
    const float* eb     = (const float*)d_in[8];
    float* out = (float*)d_out;

    void *pri, *pt1, *pt2, *pro;
    cudaGetSymbolAddress(&pri, g_routed_in);
    cudaGetSymbolAddress(&pt1, g_tmp1);
    cudaGetSymbolAddress(&pt2, g_tmp2);
    cudaGetSymbolAddress(&pro, g_routed_out);
    float* RI = (float*)pri;
    float* T1 = (float*)pt1;
    float* T2 = (float*)pt2;
    float* RO = (float*)pro;

    // routing
    zero_counts_kernel<<<1, 32>>>();
    router_kernel<<<TOK / 8, 256>>>(x, gate_w, eb);
    offsets_kernel<<<1, 1>>>();
    zeropad_kernel<<<MAXROWS, 256>>>();
    dispatch_kernel<<<RROWS, 256>>>(x);

    // routed experts: h = silu(RI@w1) * (RI@w3); RO = h @ w2
    dim3 gRH(HID / 128, MAXTILES);   // N=HID tiles x row tiles
    dim3 gRD(DIM / 128, MAXTILES);
    sgemm128_kernel<true><<<gRH, 256>>>(RI, w1, T1, HID, DIM, (size_t)DIM * HID);
    sgemm128_kernel<true><<<gRH, 256>>>(RI, w3, T2, HID, DIM, (size_t)DIM * HID);
    silu_mul_kernel<<<(int)(((size_t)MAXROWS * HID / 4) / 256), 256>>>(
        T1, T2, T1, (long)MAXROWS * HID / 4);
    sgemm128_kernel<true><<<gRD, 256>>>(T1, w2, RO, DIM, HID, (size_t)HID * DIM);

    // shared expert: out = (silu(x@sw1) * (x@sw3)) @ sw2
    dim3 gSH(HID / 128, TOK / 128);
    dim3 gSD(DIM / 128, TOK / 128);
    sgemm128_kernel<false><<<gSH, 256>>>(x, sw1, T2, HID, DIM, 0);
    sgemm128_kernel<false><<<gSH, 256>>>(x, sw3, T1, HID, DIM, 0);
    silu_mul_kernel<<<(int)(((size_t)TOK * HID / 4) / 256), 256>>>(
        T2, T1, T2, (long)TOK * HID / 4);
    sgemm128_kernel<false><<<gSD, 256>>>(T2, sw2, out, DIM, HID, 0);

    // combine routed contributions into out (deterministic, no atomics)
    combine_kernel<<<TOK, 256>>>(out);
}